// round 7
// baseline (speedup 1.0000x reference)
#include <cuda_runtime.h>
#include <cuda_fp16.h>
#include <cstdint>

// Problem constants
static constexpr int B_ = 32, T_ = 200, K_ = 50, D_ = 100;
static constexpr int NTILES = B_ * T_;   // 6400
static constexpr int THREADS = 512;      // 16 warps: 2 independent halves of 8

// fp16 strides (halfs). Bank patterns verified conflict-free (see analysis).
static constexpr int SWH = 216;   // Wht  [112 x 216]
static constexpr int SWR = 120;   // Wrel [112 x 120]
static constexpr int SXH = 216;   // X   fp16 [50 x 216] (cols 200..215 zero)
static constexpr int SRH = 120;   // REL fp16 [50 x 120] (cols 100..119 zero)

static constexpr int XH_TILE = 50 * SXH * 2;   // 21600 bytes per buffer
static constexpr int RH_TILE = 50 * SRH * 2;   // 12000 bytes per buffer

static constexpr int OFF_WHT  = 0;                  // 48384
static constexpr int OFF_WREL = 48384;              // 26880 -> 75264
static constexpr int OFF_XH   = 75264;              // 2 halves * 2 bufs * 21600 -> 161664
static constexpr int OFF_RELH = 161664;             // 2 * 2 * 12000 -> 209664
static constexpr int OFF_BHT  = 209664;             // 448
static constexpr int OFF_BREL = 210112;             // 448 -> 210560
static constexpr int OFF_EP   = 210560;             // 2*128 fl -> 211584
static constexpr int OFF_AL   = 211584;             // 2*64 fl  -> 212096
static constexpr int OFF_IDS  = 212096;             // 2 halves * 2 bufs * 152 ints -> 214528
static constexpr int SMEM_BYTES = 214528;
static constexpr int ZERO_BYTES = OFF_BHT;          // weights + staging pads must be 0

__device__ __forceinline__ void mma16816(float& c0, float& c1, float& c2, float& c3,
                                         uint32_t a0, uint32_t a1, uint32_t a2, uint32_t a3,
                                         uint32_t b0, uint32_t b1) {
    asm volatile("mma.sync.aligned.m16n8k16.row.col.f32.f16.f16.f32 "
                 "{%0,%1,%2,%3}, {%4,%5,%6,%7}, {%8,%9}, {%0,%1,%2,%3};"
                 : "+f"(c0), "+f"(c1), "+f"(c2), "+f"(c3)
                 : "r"(a0), "r"(a1), "r"(a2), "r"(a3), "r"(b0), "r"(b1));
}
__device__ __forceinline__ uint32_t f2h2(float a, float b) {
    __half2 h = __floats2half2_rn(a, b);
    return *reinterpret_cast<uint32_t*>(&h);
}
__device__ __forceinline__ float tanh_approx(float x) {
    float y;
    asm("tanh.approx.f32 %0, %1;" : "=f"(y) : "f"(x));
    return y;
}
#define BARH(s) asm volatile("bar.sync %0, 256;" :: "r"((s) + 1) : "memory")

extern __shared__ __align__(16) unsigned char smem_raw[];

__global__ __launch_bounds__(THREADS, 1)
void outer_encoder_mma(const unsigned int* __restrict__ idsw,
                       const float* __restrict__ emb,
                       const float* __restrict__ Wht,
                       const float* __restrict__ bht,
                       const float* __restrict__ Wrel,
                       const float* __restrict__ brel,
                       float* __restrict__ out) {
    unsigned char* sm = smem_raw;
    const int tid = threadIdx.x, w = tid >> 5, lane = tid & 31;
    const int s = tid >> 8;               // half-slot (0/1)
    const int ht = tid & 255;             // thread-in-half
    const int wh = w & 7;                 // warp-in-half
    const int gid = lane >> 2, tig = lane & 3;

    float* sbht = (float*)(sm + OFF_BHT);
    float* sbrl = (float*)(sm + OFF_BREL);
    float* sEp  = (float*)(sm + OFF_EP)  + s * 128;
    float* sAl  = (float*)(sm + OFF_AL)  + s * 64;
    int*   sIds = (int*)  (sm + OFF_IDS) + s * 304;               // two buffers of 152
    __half* sXh = (__half*)(sm + OFF_XH   + s * 2 * XH_TILE);     // two buffers
    __half* sRh = (__half*)(sm + OFF_RELH + s * 2 * RH_TILE);

    // ---- zero weights + staging (pad cols must be 0 and stay 0) ----
    for (int i = tid; i < ZERO_BYTES / 16; i += THREADS)
        ((uint4*)sm)[i] = make_uint4(0, 0, 0, 0);
    __syncthreads();

    // ---- weights -> fp16 smem ----
    {
        const float4* g = (const float4*)Wht;              // [100][200] -> 5000 f4
        for (int i = tid; i < 5000; i += THREADS) {
            int d = i / 50, c4 = i % 50;
            float4 v = __ldg(&g[i]);
            uint2 hv; hv.x = f2h2(v.x, v.y); hv.y = f2h2(v.z, v.w);
            *(uint2*)(sm + OFF_WHT + (d * SWH + c4 * 4) * 2) = hv;
        }
        const float4* gr = (const float4*)Wrel;            // [100][100] -> 2500 f4
        for (int i = tid; i < 2500; i += THREADS) {
            int d = i / 25, c4 = i % 25;
            float4 v = __ldg(&gr[i]);
            uint2 hv; hv.x = f2h2(v.x, v.y); hv.y = f2h2(v.z, v.w);
            *(uint2*)(sm + OFF_WREL + (d * SWR + c4 * 4) * 2) = hv;
        }
        if (tid < 112) {
            sbht[tid] = (tid < D_) ? bht[tid]  : 0.f;
            sbrl[tid] = (tid < D_) ? brel[tid] : 0.f;
        }
    }
    const int is64 = ((idsw[1] | idsw[3] | idsw[5] | idsw[7]) == 0) ? 1 : 0;
    __syncthreads();   // after this the two halves decouple

    const int mt = w & 3, nh = (w >> 2) & 1;
    const int arow = mt * 16 + gid;
    const int row0 = (arow     < K_) ? arow     : (K_ - 1);
    const int row1 = (arow + 8 < K_) ? arow + 8 : (K_ - 1);
    const __half* pWH = (const __half*)(sm + OFF_WHT);
    const __half* pWR = (const __half*)(sm + OFF_WREL);

    const int hs = blockIdx.x * 2 + s;
    const int NH = gridDim.x * 2;

    // ---- prologue: ids + LDG gather for the first tile into buffer 0 ----
    if (ht < 150) {
        const long long e = (long long)hs * 150 + ht;
        sIds[ht] = (int)(is64 ? idsw[2 * e] : idsw[e]);
    }
    BARH(s);
    if (lane < 25) {
#pragma unroll 2
        for (int t = wh; t < 50; t += 8) {
            const int id = sIds[t * 3 + 1];
            float4 v = __ldg((const float4*)(emb + (long long)id * D_) + lane);
            uint2 hv; hv.x = f2h2(v.x, v.y); hv.y = f2h2(v.z, v.w);
            *(uint2*)(sRh + t * SRH + lane * 4) = hv;
        }
#pragma unroll 2
        for (int t = wh; t < 100; t += 8) {
            const int k = t >> 1, h = t & 1;
            const int id = sIds[k * 3 + (h ? 2 : 0)];
            float4 v = __ldg((const float4*)(emb + (long long)id * D_) + lane);
            uint2 hv; hv.x = f2h2(v.x, v.y); hv.y = f2h2(v.z, v.w);
            *(uint2*)(sXh + k * SXH + h * 100 + lane * 4) = hv;
        }
    }
    BARH(s);

    int pp = 0;
    for (int tile = hs; tile < NTILES; tile += NH) {
        const bool has_next = (tile + NH) < NTILES;
        int* curIds = sIds + pp * 152;
        int* nxtIds = sIds + (pp ^ 1) * 152;
        const __half* pX = sXh + pp * (XH_TILE / 2);
        const __half* pR = sRh + pp * (RH_TILE / 2);
        __half* nX = sXh + (pp ^ 1) * (XH_TILE / 2);
        __half* nR = sRh + (pp ^ 1) * (RH_TILE / 2);

        // next-tile ids: LDG now, STS before mid barrier (latency hidden under GEMM2)
        int rid = 0;
        const bool pre = has_next && (ht < 150);
        if (pre) {
            const long long e = (long long)(tile + NH) * 150 + ht;
            rid = (int)(is64 ? idsw[2 * e] : idsw[e]);
        }

        float acc1[7][4], acc2[7][4];
#pragma unroll
        for (int nt = 0; nt < 7; nt++)
#pragma unroll
            for (int j = 0; j < 4; j++) { acc1[nt][j] = 0.f; acc2[nt][j] = 0.f; }

        {   // GEMM2: D2 = REL[64x112] @ Wrel[112x112]^T  (fp16 A from smem)
            const __half* pA0 = pR + row0 * SRH;
            const __half* pA1 = pR + row1 * SRH;
#pragma unroll
            for (int ks = 0; ks < 7; ks++) {
                const int k0 = ks * 16 + tig * 2;
                uint32_t a0 = *(const uint32_t*)(pA0 + k0);
                uint32_t a1 = *(const uint32_t*)(pA1 + k0);
                uint32_t a2 = *(const uint32_t*)(pA0 + k0 + 8);
                uint32_t a3 = *(const uint32_t*)(pA1 + k0 + 8);
#pragma unroll
                for (int nt = 0; nt < 7; nt++) {
                    const int brow = nh * 56 + nt * 8 + gid;
                    uint32_t b0 = *(const uint32_t*)(pWR + brow * SWR + k0);
                    uint32_t b1 = *(const uint32_t*)(pWR + brow * SWR + k0 + 8);
                    mma16816(acc2[nt][0], acc2[nt][1], acc2[nt][2], acc2[nt][3],
                             a0, a1, a2, a3, b0, b1);
                }
            }
        }
        if (pre) nxtIds[ht] = rid;
        BARH(s);   // next ids visible

        // overlap: next tile's REL gather (LDG+cvt+STS fp16) under GEMM1
        if (has_next && lane < 25) {
#pragma unroll 2
            for (int t = wh; t < 50; t += 8) {
                const int id = nxtIds[t * 3 + 1];
                float4 v = __ldg((const float4*)(emb + (long long)id * D_) + lane);
                uint2 hv; hv.x = f2h2(v.x, v.y); hv.y = f2h2(v.z, v.w);
                *(uint2*)(nR + t * SRH + lane * 4) = hv;
            }
        }

        {   // GEMM1: D1 = X[64x208] @ Wht[112x208]^T  (fp16 A from smem)
            const __half* pA0 = pX + row0 * SXH;
            const __half* pA1 = pX + row1 * SXH;
#pragma unroll
            for (int ks = 0; ks < 13; ks++) {
                const int k0 = ks * 16 + tig * 2;
                uint32_t a0 = *(const uint32_t*)(pA0 + k0);
                uint32_t a1 = *(const uint32_t*)(pA1 + k0);
                uint32_t a2 = *(const uint32_t*)(pA0 + k0 + 8);
                uint32_t a3 = *(const uint32_t*)(pA1 + k0 + 8);
#pragma unroll
                for (int nt = 0; nt < 7; nt++) {
                    const int brow = nh * 56 + nt * 8 + gid;
                    uint32_t b0 = *(const uint32_t*)(pWH + brow * SWH + k0);
                    uint32_t b1 = *(const uint32_t*)(pWH + brow * SWH + k0 + 8);
                    mma16816(acc1[nt][0], acc1[nt][1], acc1[nt][2], acc1[nt][3],
                             a0, a1, a2, a3, b0, b1);
                }
            }
        }

        // ---- fused epilogue: e partials (pad cols contribute 0) ----
        {
            float e0 = 0.f, e1 = 0.f;
#pragma unroll
            for (int nt = 0; nt < 7; nt++) {
                const int c0 = nh * 56 + nt * 8 + tig * 2;
                const float bh0 = sbht[c0], bh1 = sbht[c0 + 1];
                const float br0 = sbrl[c0], br1 = sbrl[c0 + 1];
                e0 += tanh_approx(acc1[nt][0] + bh0) * (acc2[nt][0] + br0)
                    + tanh_approx(acc1[nt][1] + bh1) * (acc2[nt][1] + br1);
                e1 += tanh_approx(acc1[nt][2] + bh0) * (acc2[nt][2] + br0)
                    + tanh_approx(acc1[nt][3] + bh1) * (acc2[nt][3] + br1);
            }
            e0 += __shfl_xor_sync(0xffffffffu, e0, 1);
            e0 += __shfl_xor_sync(0xffffffffu, e0, 2);
            e1 += __shfl_xor_sync(0xffffffffu, e1, 1);
            e1 += __shfl_xor_sync(0xffffffffu, e1, 2);
            if (tig == 0) {
                sEp[nh * 64 + arow]     = e0;
                sEp[nh * 64 + arow + 8] = e1;
            }
        }
        BARH(s);   // sEp ready

        // warp 0: softmax.  warps 1..7: next tile's X gather (overlapped).
        if (wh == 0) {
            float v0 = (lane < K_) ? (sEp[lane] + sEp[64 + lane]) : -1e30f;
            float v1 = (lane + 32 < K_) ? (sEp[lane + 32] + sEp[64 + lane + 32]) : -1e30f;
            float m = fmaxf(v0, v1);
#pragma unroll
            for (int off = 16; off > 0; off >>= 1)
                m = fmaxf(m, __shfl_xor_sync(0xffffffffu, m, off));
            float x0 = (lane < K_) ? __expf(v0 - m) : 0.f;
            float x1 = (lane + 32 < K_) ? __expf(v1 - m) : 0.f;
            float su = x0 + x1;
#pragma unroll
            for (int off = 16; off > 0; off >>= 1)
                su += __shfl_xor_sync(0xffffffffu, su, off);
            float inv = __fdividef(1.f, su);
            if (lane < K_)      sAl[lane]      = x0 * inv;
            if (lane + 32 < K_) sAl[lane + 32] = x1 * inv;
        } else if (has_next && lane < 25) {
#pragma unroll 2
            for (int t = wh - 1; t < 100; t += 7) {
                const int k = t >> 1, h = t & 1;
                const int id = nxtIds[k * 3 + (h ? 2 : 0)];
                float4 v = __ldg((const float4*)(emb + (long long)id * D_) + lane);
                uint2 hv; hv.x = f2h2(v.x, v.y); hv.y = f2h2(v.z, v.w);
                *(uint2*)(nX + k * SXH + h * 100 + lane * 4) = hv;
            }
        }
        BARH(s);   // alpha ready

        // ---- weighted sum: pipelined emb re-reads (L2-hot, coalesced) ----
        if (ht < 200) {
            const int part = (ht < 100) ? 0 : 2;
            const int col  = (ht < 100) ? ht : ht - 100;
            const float* ebase = emb + col;
            float acc = 0.f;
#pragma unroll
            for (int k0 = 0; k0 < K_; k0 += 10) {
                float v[10];
#pragma unroll
                for (int j = 0; j < 10; j++) {
                    const int id = curIds[(k0 + j) * 3 + part];
                    v[j] = __ldg(ebase + (long long)id * D_);
                }
#pragma unroll
                for (int j = 0; j < 10; j++) acc += sAl[k0 + j] * v[j];
            }
            out[(long long)tile * 200 + ht] = acc;
        }
        BARH(s);   // staging STS complete before next iter's GEMM reads; sAl/curIds safe
        pp ^= 1;
    }
}

extern "C" void kernel_launch(void* const* d_in, const int* in_sizes, int n_in,
                              void* d_out, int out_size) {
    const unsigned int* ids = nullptr;
    const float *emb = nullptr, *Wht = nullptr, *Wrel = nullptr;
    const float *bht = nullptr, *brel = nullptr;

    for (int i = 0; i < n_in; i++) {
        const int sz = in_sizes[i];
        if      (sz == B_ * T_ * K_ * 3) ids  = (const unsigned int*)d_in[i];
        else if (sz == 500000 * D_)      emb  = (const float*)d_in[i];
        else if (sz == D_ * 2 * D_)      Wht  = (const float*)d_in[i];
        else if (sz == D_ * D_)          Wrel = (const float*)d_in[i];
        else if (sz == D_) {
            if (!bht) bht = (const float*)d_in[i];
            else      brel = (const float*)d_in[i];
        }
    }

    int dev = 0;
    cudaGetDevice(&dev);
    int sms = 148;
    cudaDeviceGetAttribute(&sms, cudaDevAttrMultiProcessorCount, dev);
    if (sms <= 0) sms = 148;

    cudaFuncSetAttribute(outer_encoder_mma,
                         cudaFuncAttributeMaxDynamicSharedMemorySize, SMEM_BYTES);
    outer_encoder_mma<<<sms, THREADS, SMEM_BYTES>>>(
        ids, emb, Wht, bht, Wrel, brel, (float*)d_out);
}

// round 8
// speedup vs baseline: 1.7344x; 1.7344x over previous
#include <cuda_runtime.h>
#include <cuda_fp16.h>
#include <cstdint>

// Problem constants
static constexpr int B_ = 32, T_ = 200, K_ = 50, D_ = 100;
static constexpr int NTILES = B_ * T_;   // 6400
static constexpr int THREADS = 512;      // 16 warps: 2 independent halves of 8

// fp16 weight strides (halfs); fp32 staging strides (floats). Bank patterns verified CF.
static constexpr int SWH = 216;   // Wht  [112 x 216]
static constexpr int SWR = 120;   // Wrel [112 x 120]
static constexpr int SXF = 216;   // X   [50 x 216] fp32 (cols 200..215 zero)
static constexpr int SRF = 120;   // REL [50 x 120] fp32 (cols 100..119 zero)

static constexpr int XF_TILE = 50 * SXF * 4;   // 43200
static constexpr int RF_TILE = 50 * SRF * 4;   // 24000

static constexpr int OFF_WHT  = 0;                  // 48384
static constexpr int OFF_WREL = 48384;              // 26880 -> 75264
static constexpr int OFF_XF   = 75264;              // 2*43200 -> 161664
static constexpr int OFF_RELF = 161664;             // 2*24000 -> 209664
static constexpr int OFF_BHT  = 209664;             // 448
static constexpr int OFF_BREL = 210112;             // 448 -> 210560
static constexpr int OFF_EP   = 210560;             // 2*128 fl -> 211584
static constexpr int OFF_IDS  = 211584;             // 2 halves * 2 bufs * 152 ints -> 214016
static constexpr int SMEM_BYTES = 214016;
static constexpr int ZERO_BYTES = OFF_BHT;          // weights + staging pads must be 0

__device__ __forceinline__ void mma16816(float& c0, float& c1, float& c2, float& c3,
                                         uint32_t a0, uint32_t a1, uint32_t a2, uint32_t a3,
                                         uint32_t b0, uint32_t b1) {
    asm volatile("mma.sync.aligned.m16n8k16.row.col.f32.f16.f16.f32 "
                 "{%0,%1,%2,%3}, {%4,%5,%6,%7}, {%8,%9}, {%0,%1,%2,%3};"
                 : "+f"(c0), "+f"(c1), "+f"(c2), "+f"(c3)
                 : "r"(a0), "r"(a1), "r"(a2), "r"(a3), "r"(b0), "r"(b1));
}
__device__ __forceinline__ uint32_t f2h2(float a, float b) {
    __half2 h = __floats2half2_rn(a, b);
    return *reinterpret_cast<uint32_t*>(&h);
}
__device__ __forceinline__ float tanh_approx(float x) {
    float y;
    asm("tanh.approx.f32 %0, %1;" : "=f"(y) : "f"(x));
    return y;
}
__device__ __forceinline__ uint32_t smem_u32(const void* p) {
    uint32_t a;
    asm("{ .reg .u64 t; cvta.to.shared.u64 t, %1; cvt.u32.u64 %0, t; }" : "=r"(a) : "l"(p));
    return a;
}
__device__ __forceinline__ void cp_async16(uint32_t dst, const void* src) {
    asm volatile("cp.async.cg.shared.global [%0], [%1], 16;" :: "r"(dst), "l"(src) : "memory");
}
#define CP_COMMIT() asm volatile("cp.async.commit_group;" ::: "memory")
#define CP_WAIT0()  asm volatile("cp.async.wait_group 0;" ::: "memory")
#define BARH(s)     asm volatile("bar.sync %0, 256;" :: "r"((s) + 1) : "memory")

extern __shared__ __align__(16) unsigned char smem_raw[];

__global__ __launch_bounds__(THREADS, 1)
void outer_encoder_mma(const unsigned int* __restrict__ idsw,
                       const float* __restrict__ emb,
                       const float* __restrict__ Wht,
                       const float* __restrict__ bht,
                       const float* __restrict__ Wrel,
                       const float* __restrict__ brel,
                       float* __restrict__ out) {
    unsigned char* sm = smem_raw;
    const uint32_t sb = smem_u32(sm);
    const int tid = threadIdx.x, w = tid >> 5, lane = tid & 31;
    const int s = tid >> 8;               // half-slot (0/1)
    const int ht = tid & 255;             // thread-in-half
    const int wh = w & 7;                 // warp-in-half
    const int gid = lane >> 2, tig = lane & 3;

    float* sbht = (float*)(sm + OFF_BHT);
    float* sbrl = (float*)(sm + OFF_BREL);
    float* sEp  = (float*)(sm + OFF_EP)  + s * 128;
    int*   sIds = (int*)  (sm + OFF_IDS) + s * 304;   // two buffers of 152
    float* sXf  = (float*)(sm + OFF_XF   + s * XF_TILE);
    float* sRf  = (float*)(sm + OFF_RELF + s * RF_TILE);

    // ---- zero weights + staging (pads must be 0 and stay 0) ----
    for (int i = tid; i < ZERO_BYTES / 16; i += THREADS)
        ((uint4*)sm)[i] = make_uint4(0, 0, 0, 0);
    __syncthreads();

    // ---- weights -> fp16 smem ----
    {
        const float4* g = (const float4*)Wht;              // [100][200] -> 5000 f4
        for (int i = tid; i < 5000; i += THREADS) {
            int d = i / 50, c4 = i % 50;
            float4 v = __ldg(&g[i]);
            uint2 hv; hv.x = f2h2(v.x, v.y); hv.y = f2h2(v.z, v.w);
            *(uint2*)(sm + OFF_WHT + (d * SWH + c4 * 4) * 2) = hv;
        }
        const float4* gr = (const float4*)Wrel;            // [100][100] -> 2500 f4
        for (int i = tid; i < 2500; i += THREADS) {
            int d = i / 25, c4 = i % 25;
            float4 v = __ldg(&gr[i]);
            uint2 hv; hv.x = f2h2(v.x, v.y); hv.y = f2h2(v.z, v.w);
            *(uint2*)(sm + OFF_WREL + (d * SWR + c4 * 4) * 2) = hv;
        }
        if (tid < 112) {
            sbht[tid] = (tid < D_) ? bht[tid]  : 0.f;
            sbrl[tid] = (tid < D_) ? brel[tid] : 0.f;
        }
    }
    const int is64 = ((idsw[1] | idsw[3] | idsw[5] | idsw[7]) == 0) ? 1 : 0;
    __syncthreads();   // after this the two halves decouple

    const int mt = w & 3, nh = (w >> 2) & 1;
    const int arow = mt * 16 + gid;
    const int row0 = (arow     < K_) ? arow     : (K_ - 1);
    const int row1 = (arow + 8 < K_) ? arow + 8 : (K_ - 1);
    const __half* pWH = (const __half*)(sm + OFF_WHT);
    const __half* pWR = (const __half*)(sm + OFF_WREL);
    const uint32_t dXb = sb + OFF_XF   + s * XF_TILE + lane * 16;
    const uint32_t dRb = sb + OFF_RELF + s * RF_TILE + lane * 16;

    const int hs = blockIdx.x * 2 + s;
    const int NH = gridDim.x * 2;

    // wsum role (constant per thread); clamp inactive threads to a safe column
    const int wpart = (ht < 100) ? 0 : 2;
    const int wcol  = (ht < 100) ? ht : ((ht < 200) ? ht - 100 : 0);

    // ---- prologue: ids + gather for the first tile ----
    if (ht < 150) {
        const long long e = (long long)hs * 150 + ht;
        sIds[ht] = (int)(is64 ? idsw[2 * e] : idsw[e]);
    }
    BARH(s);
    if (lane < 25) {
        for (int task = wh; task < 50; task += 8) {
            const int id = sIds[task * 3 + 1];
            cp_async16(dRb + task * SRF * 4,
                       (const char*)emb + (long long)id * 400 + lane * 16);
        }
        for (int task = wh; task < 100; task += 8) {
            const int k = task >> 1, h = task & 1;
            const int id = sIds[k * 3 + (h ? 2 : 0)];
            cp_async16(dXb + (k * SXF + h * 100) * 4,
                       (const char*)emb + (long long)id * 400 + lane * 16);
        }
    }
    CP_COMMIT();

    int pp = 0;
    for (int tile = hs; tile < NTILES; tile += NH) {
        const bool has_next = (tile + NH) < NTILES;
        int* curIds = sIds + pp * 152;
        int* nxtIds = sIds + (pp ^ 1) * 152;

        CP_WAIT0();
        BARH(s);   // staged data + previous-phase smem reads ordered

        // next-tile ids: LDG now, STS before mid barrier (latency hidden under GEMM2)
        int rid = 0;
        const bool pre = has_next && (ht < 150);
        if (pre) {
            const long long e = (long long)(tile + NH) * 150 + ht;
            rid = (int)(is64 ? idsw[2 * e] : idsw[e]);
        }

        float acc1[7][4], acc2[7][4];
#pragma unroll
        for (int nt = 0; nt < 7; nt++)
#pragma unroll
            for (int j = 0; j < 4; j++) { acc1[nt][j] = 0.f; acc2[nt][j] = 0.f; }

        {   // GEMM2: D2 = REL[64x112] @ Wrel[112x112]^T
            const float* pA0 = sRf + row0 * SRF;
            const float* pA1 = sRf + row1 * SRF;
#pragma unroll
            for (int ks = 0; ks < 7; ks++) {
                const int k0 = ks * 16 + tig * 2;
                float2 f0 = *(const float2*)(pA0 + k0);
                float2 f1 = *(const float2*)(pA1 + k0);
                float2 f2 = *(const float2*)(pA0 + k0 + 8);
                float2 f3 = *(const float2*)(pA1 + k0 + 8);
                uint32_t a0 = f2h2(f0.x, f0.y), a1 = f2h2(f1.x, f1.y);
                uint32_t a2 = f2h2(f2.x, f2.y), a3 = f2h2(f3.x, f3.y);
#pragma unroll
                for (int nt = 0; nt < 7; nt++) {
                    const int brow = nh * 56 + nt * 8 + gid;
                    uint32_t b0 = *(const uint32_t*)(pWR + brow * SWR + k0);
                    uint32_t b1 = *(const uint32_t*)(pWR + brow * SWR + k0 + 8);
                    mma16816(acc2[nt][0], acc2[nt][1], acc2[nt][2], acc2[nt][3],
                             a0, a1, a2, a3, b0, b1);
                }
            }
        }
        if (pre) nxtIds[ht] = rid;
        BARH(s);   // all warps done with sRf; next ids visible

        // overlap: next tile's REL gather streams in under GEMM1 + epilogue
        if (has_next && lane < 25) {
            for (int task = wh; task < 50; task += 8) {
                const int id = nxtIds[task * 3 + 1];
                cp_async16(dRb + task * SRF * 4,
                           (const char*)emb + (long long)id * 400 + lane * 16);
            }
        }

        {   // GEMM1: D1 = X[64x208] @ Wht[112x208]^T
            const float* pA0 = sXf + row0 * SXF;
            const float* pA1 = sXf + row1 * SXF;
#pragma unroll
            for (int ks = 0; ks < 13; ks++) {
                const int k0 = ks * 16 + tig * 2;
                float2 f0 = *(const float2*)(pA0 + k0);
                float2 f1 = *(const float2*)(pA1 + k0);
                float2 f2 = *(const float2*)(pA0 + k0 + 8);
                float2 f3 = *(const float2*)(pA1 + k0 + 8);
                uint32_t a0 = f2h2(f0.x, f0.y), a1 = f2h2(f1.x, f1.y);
                uint32_t a2 = f2h2(f2.x, f2.y), a3 = f2h2(f3.x, f3.y);
#pragma unroll
                for (int nt = 0; nt < 7; nt++) {
                    const int brow = nh * 56 + nt * 8 + gid;
                    uint32_t b0 = *(const uint32_t*)(pWH + brow * SWH + k0);
                    uint32_t b1 = *(const uint32_t*)(pWH + brow * SWH + k0 + 8);
                    mma16816(acc1[nt][0], acc1[nt][1], acc1[nt][2], acc1[nt][3],
                             a0, a1, a2, a3, b0, b1);
                }
            }
        }

        // ---- fused epilogue: e partials (pad cols contribute 0) ----
        {
            float e0 = 0.f, e1 = 0.f;
#pragma unroll
            for (int nt = 0; nt < 7; nt++) {
                const int c0 = nh * 56 + nt * 8 + tig * 2;
                const float bh0 = sbht[c0], bh1 = sbht[c0 + 1];
                const float br0 = sbrl[c0], br1 = sbrl[c0 + 1];
                e0 += tanh_approx(acc1[nt][0] + bh0) * (acc2[nt][0] + br0)
                    + tanh_approx(acc1[nt][1] + bh1) * (acc2[nt][1] + br1);
                e1 += tanh_approx(acc1[nt][2] + bh0) * (acc2[nt][2] + br0)
                    + tanh_approx(acc1[nt][3] + bh1) * (acc2[nt][3] + br1);
            }
            e0 += __shfl_xor_sync(0xffffffffu, e0, 1);
            e0 += __shfl_xor_sync(0xffffffffu, e0, 2);
            e1 += __shfl_xor_sync(0xffffffffu, e1, 1);
            e1 += __shfl_xor_sync(0xffffffffu, e1, 2);
            if (tig == 0) {
                sEp[nh * 64 + arow]     = e0;
                sEp[nh * 64 + arow + 8] = e1;
            }
        }
        BARH(s);   // sXf free for overwrite; sEp ready

        // overlap: next tile's X gather streams in under softmax + wsum
        if (has_next && lane < 25) {
            for (int task = wh; task < 100; task += 8) {
                const int k = task >> 1, h = task & 1;
                const int id = nxtIds[k * 3 + (h ? 2 : 0)];
                cp_async16(dXb + (k * SXF + h * 100) * 4,
                           (const char*)emb + (long long)id * 400 + lane * 16);
            }
        }
        CP_COMMIT();

        // ---- softmax (redundant per-warp, registers only) + fused weighted sum ----
        {
            // every warp computes alpha for lanes (lane) and (lane+32)
            float v0 = (lane < K_) ? (sEp[lane] + sEp[64 + lane]) : -1e30f;
            float v1 = (lane + 32 < K_) ? (sEp[lane + 32] + sEp[64 + lane + 32]) : -1e30f;
            float m = fmaxf(v0, v1);
#pragma unroll
            for (int off = 16; off > 0; off >>= 1)
                m = fmaxf(m, __shfl_xor_sync(0xffffffffu, m, off));
            float x0 = (lane < K_) ? __expf(v0 - m) : 0.f;
            float x1 = (lane + 32 < K_) ? __expf(v1 - m) : 0.f;
            float su = x0 + x1;
#pragma unroll
            for (int off = 16; off > 0; off >>= 1)
                su += __shfl_xor_sync(0xffffffffu, su, off);
            const float inv = __fdividef(1.f, su);
            const float al0 = x0 * inv;        // alpha[lane]
            const float al1 = x1 * inv;        // alpha[lane+32]

            // wsum: thread owns output column wcol of part wpart (MLP=10 LDG batches)
            if (wh < 7) {   // warps 0..6 cover ht<224 (>=200 lanes store-gated)
                const float* ebase = emb + wcol;
                float acc = 0.f;
#pragma unroll
                for (int k0 = 0; k0 < K_; k0 += 10) {
                    float v[10];
#pragma unroll
                    for (int j = 0; j < 10; j++) {
                        const int id = curIds[(k0 + j) * 3 + wpart];
                        v[j] = __ldg(ebase + (long long)id * D_);
                    }
#pragma unroll
                    for (int j = 0; j < 10; j++) {
                        const int k = k0 + j;
                        const float al = (k < 32) ? __shfl_sync(0xffffffffu, al0, k)
                                                  : __shfl_sync(0xffffffffu, al1, k - 32);
                        acc += al * v[j];
                    }
                }
                if (ht < 200) out[(long long)tile * 200 + ht] = acc;
            }
        }
        // no trailing barrier: the next iteration's head BARH orders
        // sEp reads vs next epilogue writes and curIds reads vs next id stores.
        pp ^= 1;
    }
}

extern "C" void kernel_launch(void* const* d_in, const int* in_sizes, int n_in,
                              void* d_out, int out_size) {
    const unsigned int* ids = nullptr;
    const float *emb = nullptr, *Wht = nullptr, *Wrel = nullptr;
    const float *bht = nullptr, *brel = nullptr;

    for (int i = 0; i < n_in; i++) {
        const int sz = in_sizes[i];
        if      (sz == B_ * T_ * K_ * 3) ids  = (const unsigned int*)d_in[i];
        else if (sz == 500000 * D_)      emb  = (const float*)d_in[i];
        else if (sz == D_ * 2 * D_)      Wht  = (const float*)d_in[i];
        else if (sz == D_ * D_)          Wrel = (const float*)d_in[i];
        else if (sz == D_) {
            if (!bht) bht = (const float*)d_in[i];
            else      brel = (const float*)d_in[i];
        }
    }

    int dev = 0;
    cudaGetDevice(&dev);
    int sms = 148;
    cudaDeviceGetAttribute(&sms, cudaDevAttrMultiProcessorCount, dev);
    if (sms <= 0) sms = 148;

    cudaFuncSetAttribute(outer_encoder_mma,
                         cudaFuncAttributeMaxDynamicSharedMemorySize, SMEM_BYTES);
    outer_encoder_mma<<<sms, THREADS, SMEM_BYTES>>>(
        ids, emb, Wht, bht, Wrel, brel, (float*)d_out);
}

// round 9
// speedup vs baseline: 1.7794x; 1.0260x over previous
#include <cuda_runtime.h>
#include <cuda_fp16.h>
#include <cstdint>

// Problem constants
static constexpr int B_ = 32, T_ = 200, K_ = 50, D_ = 100;
static constexpr int NTILES = B_ * T_;   // 6400
static constexpr int THREADS = 512;      // 16 warps: 2 independent halves of 8

// fp16 weight strides (halfs); fp32 staging strides (floats). Bank patterns verified CF.
static constexpr int SWH = 216;   // Wht  [112 x 216]
static constexpr int SWR = 120;   // Wrel [112 x 120]
static constexpr int SXF = 216;   // X   [50 x 216] fp32 (cols 200..215 zero)
static constexpr int SRF = 120;   // REL [50 x 120] fp32 (cols 100..119 zero)

static constexpr int XF_TILE = 50 * SXF * 4;   // 43200
static constexpr int RF_TILE = 50 * SRF * 4;   // 24000

static constexpr int OFF_WHT  = 0;                  // 48384
static constexpr int OFF_WREL = 48384;              // 26880 -> 75264
static constexpr int OFF_XF   = 75264;              // 2*43200 -> 161664
static constexpr int OFF_RELF = 161664;             // 2*24000 -> 209664
static constexpr int OFF_BHT  = 209664;             // 448
static constexpr int OFF_BREL = 210112;             // 448 -> 210560
static constexpr int OFF_EP   = 210560;             // 2*128 fl -> 211584
static constexpr int OFF_IDS  = 211584;             // 2 halves * 2 bufs * 152 ints -> 214016
static constexpr int SMEM_BYTES = 214016;
static constexpr int ZERO_BYTES = OFF_BHT;          // weights + staging pads must be 0

__device__ __forceinline__ void mma16816(float& c0, float& c1, float& c2, float& c3,
                                         uint32_t a0, uint32_t a1, uint32_t a2, uint32_t a3,
                                         uint32_t b0, uint32_t b1) {
    asm volatile("mma.sync.aligned.m16n8k16.row.col.f32.f16.f16.f32 "
                 "{%0,%1,%2,%3}, {%4,%5,%6,%7}, {%8,%9}, {%0,%1,%2,%3};"
                 : "+f"(c0), "+f"(c1), "+f"(c2), "+f"(c3)
                 : "r"(a0), "r"(a1), "r"(a2), "r"(a3), "r"(b0), "r"(b1));
}
__device__ __forceinline__ uint32_t f2h2(float a, float b) {
    __half2 h = __floats2half2_rn(a, b);
    return *reinterpret_cast<uint32_t*>(&h);
}
__device__ __forceinline__ float tanh_approx(float x) {
    float y;
    asm("tanh.approx.f32 %0, %1;" : "=f"(y) : "f"(x));
    return y;
}
__device__ __forceinline__ uint32_t smem_u32(const void* p) {
    uint32_t a;
    asm("{ .reg .u64 t; cvta.to.shared.u64 t, %1; cvt.u32.u64 %0, t; }" : "=r"(a) : "l"(p));
    return a;
}
__device__ __forceinline__ void cp_async16(uint32_t dst, const void* src) {
    asm volatile("cp.async.cg.shared.global [%0], [%1], 16;" :: "r"(dst), "l"(src) : "memory");
}
#define CP_COMMIT() asm volatile("cp.async.commit_group;" ::: "memory")
#define CP_WAIT0()  asm volatile("cp.async.wait_group 0;" ::: "memory")
#define BARH(s)     asm volatile("bar.sync %0, 256;" :: "r"((s) + 1) : "memory")

extern __shared__ __align__(16) unsigned char smem_raw[];

__global__ __launch_bounds__(THREADS, 1)
void outer_encoder_mma(const unsigned int* __restrict__ idsw,
                       const float* __restrict__ emb,
                       const float* __restrict__ Wht,
                       const float* __restrict__ bht,
                       const float* __restrict__ Wrel,
                       const float* __restrict__ brel,
                       float* __restrict__ out) {
    unsigned char* sm = smem_raw;
    const uint32_t sb = smem_u32(sm);
    const int tid = threadIdx.x, w = tid >> 5, lane = tid & 31;
    const int s = tid >> 8;               // half-slot (0/1)
    const int ht = tid & 255;             // thread-in-half
    const int wh = w & 7;                 // warp-in-half
    const int gid = lane >> 2, tig = lane & 3;

    float* sbht = (float*)(sm + OFF_BHT);
    float* sbrl = (float*)(sm + OFF_BREL);
    float* sEp  = (float*)(sm + OFF_EP)  + s * 128;
    int*   sIds = (int*)  (sm + OFF_IDS) + s * 304;   // two buffers of 152
    float* sXf  = (float*)(sm + OFF_XF   + s * XF_TILE);
    float* sRf  = (float*)(sm + OFF_RELF + s * RF_TILE);

    // ---- zero weights + staging (pads must be 0 and stay 0) ----
    for (int i = tid; i < ZERO_BYTES / 16; i += THREADS)
        ((uint4*)sm)[i] = make_uint4(0, 0, 0, 0);
    __syncthreads();

    // ---- weights -> fp16 smem ----
    {
        const float4* g = (const float4*)Wht;              // [100][200] -> 5000 f4
        for (int i = tid; i < 5000; i += THREADS) {
            int d = i / 50, c4 = i % 50;
            float4 v = __ldg(&g[i]);
            uint2 hv; hv.x = f2h2(v.x, v.y); hv.y = f2h2(v.z, v.w);
            *(uint2*)(sm + OFF_WHT + (d * SWH + c4 * 4) * 2) = hv;
        }
        const float4* gr = (const float4*)Wrel;            // [100][100] -> 2500 f4
        for (int i = tid; i < 2500; i += THREADS) {
            int d = i / 25, c4 = i % 25;
            float4 v = __ldg(&gr[i]);
            uint2 hv; hv.x = f2h2(v.x, v.y); hv.y = f2h2(v.z, v.w);
            *(uint2*)(sm + OFF_WREL + (d * SWR + c4 * 4) * 2) = hv;
        }
        if (tid < 112) {
            sbht[tid] = (tid < D_) ? bht[tid]  : 0.f;
            sbrl[tid] = (tid < D_) ? brel[tid] : 0.f;
        }
    }
    const int is64 = ((idsw[1] | idsw[3] | idsw[5] | idsw[7]) == 0) ? 1 : 0;
    __syncthreads();   // after this the two halves decouple

    const int mt = w & 3, nh = (w >> 2) & 1;
    const int arow = mt * 16 + gid;
    const int row0 = (arow     < K_) ? arow     : (K_ - 1);
    const int row1 = (arow + 8 < K_) ? arow + 8 : (K_ - 1);
    // mt==3: rows arow+8 (56..63) all clamp to 49 and their outputs are discarded ->
    // skip those A-frag LDS entirely (copy a0/a2 instead; values irrelevant).
    const bool skipA1 = (mt == 3);
    const __half* pWH = (const __half*)(sm + OFF_WHT);
    const __half* pWR = (const __half*)(sm + OFF_WREL);
    const uint32_t dXb = sb + OFF_XF   + s * XF_TILE + lane * 16;
    const uint32_t dRb = sb + OFF_RELF + s * RF_TILE + lane * 16;

    const int hs = blockIdx.x * 2 + s;
    const int NH = gridDim.x * 2;

    // wsum role (constant per thread); clamp inactive threads to a safe column
    const int wpart = (ht < 100) ? 0 : 2;
    const int wcol  = (ht < 100) ? ht : ((ht < 200) ? ht - 100 : 0);

    // ---- prologue: ids + gather for the first tile ----
    if (ht < 150) {
        const long long e = (long long)hs * 150 + ht;
        sIds[ht] = (int)(is64 ? idsw[2 * e] : idsw[e]);
    }
    BARH(s);
    if (lane < 25) {
        for (int task = wh; task < 50; task += 8) {
            const int id = sIds[task * 3 + 1];
            cp_async16(dRb + task * SRF * 4,
                       (const char*)emb + (long long)id * 400 + lane * 16);
        }
        for (int task = wh; task < 100; task += 8) {
            const int k = task >> 1, h = task & 1;
            const int id = sIds[k * 3 + (h ? 2 : 0)];
            cp_async16(dXb + (k * SXF + h * 100) * 4,
                       (const char*)emb + (long long)id * 400 + lane * 16);
        }
    }
    CP_COMMIT();

    int pp = 0;
    for (int tile = hs; tile < NTILES; tile += NH) {
        const bool has_next = (tile + NH) < NTILES;
        int* curIds = sIds + pp * 152;
        int* nxtIds = sIds + (pp ^ 1) * 152;

        CP_WAIT0();
        BARH(s);   // staged data + previous-phase smem reads ordered

        // next-tile ids: LDG now, STS before mid barrier (latency hidden under GEMM2)
        int rid = 0;
        const bool pre = has_next && (ht < 150);
        if (pre) {
            const long long e = (long long)(tile + NH) * 150 + ht;
            rid = (int)(is64 ? idsw[2 * e] : idsw[e]);
        }

        float acc1[7][4], acc2[7][4];
#pragma unroll
        for (int nt = 0; nt < 7; nt++)
#pragma unroll
            for (int j = 0; j < 4; j++) { acc1[nt][j] = 0.f; acc2[nt][j] = 0.f; }

        {   // GEMM2: D2 = REL[64x112] @ Wrel[112x112]^T
            const float* pA0 = sRf + row0 * SRF;
            const float* pA1 = sRf + row1 * SRF;
#pragma unroll
            for (int ks = 0; ks < 7; ks++) {
                const int k0 = ks * 16 + tig * 2;
                float2 f0 = *(const float2*)(pA0 + k0);
                float2 f2 = *(const float2*)(pA0 + k0 + 8);
                float2 f1 = skipA1 ? f0 : *(const float2*)(pA1 + k0);
                float2 f3 = skipA1 ? f2 : *(const float2*)(pA1 + k0 + 8);
                uint32_t a0 = f2h2(f0.x, f0.y), a1 = f2h2(f1.x, f1.y);
                uint32_t a2 = f2h2(f2.x, f2.y), a3 = f2h2(f3.x, f3.y);
#pragma unroll
                for (int nt = 0; nt < 7; nt++) {
                    const int brow = nh * 56 + nt * 8 + gid;
                    uint32_t b0 = *(const uint32_t*)(pWR + brow * SWR + k0);
                    uint32_t b1 = *(const uint32_t*)(pWR + brow * SWR + k0 + 8);
                    mma16816(acc2[nt][0], acc2[nt][1], acc2[nt][2], acc2[nt][3],
                             a0, a1, a2, a3, b0, b1);
                }
            }
        }
        if (pre) nxtIds[ht] = rid;
        BARH(s);   // all warps done with sRf; next ids visible

        // overlap: next tile's REL gather streams in under GEMM1 + epilogue
        if (has_next && lane < 25) {
            for (int task = wh; task < 50; task += 8) {
                const int id = nxtIds[task * 3 + 1];
                cp_async16(dRb + task * SRF * 4,
                           (const char*)emb + (long long)id * 400 + lane * 16);
            }
        }

        {   // GEMM1: D1 = X[64x208] @ Wht[112x208]^T
            const float* pA0 = sXf + row0 * SXF;
            const float* pA1 = sXf + row1 * SXF;
#pragma unroll
            for (int ks = 0; ks < 13; ks++) {
                const int k0 = ks * 16 + tig * 2;
                float2 f0 = *(const float2*)(pA0 + k0);
                float2 f2 = *(const float2*)(pA0 + k0 + 8);
                float2 f1 = skipA1 ? f0 : *(const float2*)(pA1 + k0);
                float2 f3 = skipA1 ? f2 : *(const float2*)(pA1 + k0 + 8);
                uint32_t a0 = f2h2(f0.x, f0.y), a1 = f2h2(f1.x, f1.y);
                uint32_t a2 = f2h2(f2.x, f2.y), a3 = f2h2(f3.x, f3.y);
#pragma unroll
                for (int nt = 0; nt < 7; nt++) {
                    const int brow = nh * 56 + nt * 8 + gid;
                    uint32_t b0 = *(const uint32_t*)(pWH + brow * SWH + k0);
                    uint32_t b1 = *(const uint32_t*)(pWH + brow * SWH + k0 + 8);
                    mma16816(acc1[nt][0], acc1[nt][1], acc1[nt][2], acc1[nt][3],
                             a0, a1, a2, a3, b0, b1);
                }
            }
        }

        // ---- fused epilogue: e partials (pad cols contribute 0) ----
        {
            float e0 = 0.f, e1 = 0.f;
#pragma unroll
            for (int nt = 0; nt < 7; nt++) {
                const int c0 = nh * 56 + nt * 8 + tig * 2;
                const float bh0 = sbht[c0], bh1 = sbht[c0 + 1];
                const float br0 = sbrl[c0], br1 = sbrl[c0 + 1];
                e0 += tanh_approx(acc1[nt][0] + bh0) * (acc2[nt][0] + br0)
                    + tanh_approx(acc1[nt][1] + bh1) * (acc2[nt][1] + br1);
                e1 += tanh_approx(acc1[nt][2] + bh0) * (acc2[nt][2] + br0)
                    + tanh_approx(acc1[nt][3] + bh1) * (acc2[nt][3] + br1);
            }
            e0 += __shfl_xor_sync(0xffffffffu, e0, 1);
            e0 += __shfl_xor_sync(0xffffffffu, e0, 2);
            e1 += __shfl_xor_sync(0xffffffffu, e1, 1);
            e1 += __shfl_xor_sync(0xffffffffu, e1, 2);
            if (tig == 0) {
                sEp[nh * 64 + arow]     = e0;
                sEp[nh * 64 + arow + 8] = e1;
            }
        }
        BARH(s);   // sXf free for overwrite; sEp ready

        // overlap: next tile's X gather streams in under softmax + wsum
        if (has_next && lane < 25) {
            for (int task = wh; task < 100; task += 8) {
                const int k = task >> 1, h = task & 1;
                const int id = nxtIds[k * 3 + (h ? 2 : 0)];
                cp_async16(dXb + (k * SXF + h * 100) * 4,
                           (const char*)emb + (long long)id * 400 + lane * 16);
            }
        }
        CP_COMMIT();

        // ---- wsum loads batch 1 (MLP=25) issued BEFORE softmax to hide L2 latency ----
        const float* ebase = emb + wcol;
        float v1[25];
        const bool dow = (wh < 7);
        if (dow) {
#pragma unroll
            for (int j = 0; j < 25; j++) {
                const int id = curIds[j * 3 + wpart];
                v1[j] = __ldg(ebase + (long long)id * D_);
            }
        }

        // ---- softmax (redundant per-warp, registers only) ----
        float al0, al1;
        {
            float v0 = (lane < K_) ? (sEp[lane] + sEp[64 + lane]) : -1e30f;
            float vv1 = (lane + 32 < K_) ? (sEp[lane + 32] + sEp[64 + lane + 32]) : -1e30f;
            float m = fmaxf(v0, vv1);
#pragma unroll
            for (int off = 16; off > 0; off >>= 1)
                m = fmaxf(m, __shfl_xor_sync(0xffffffffu, m, off));
            float x0 = (lane < K_) ? __expf(v0 - m) : 0.f;
            float x1 = (lane + 32 < K_) ? __expf(vv1 - m) : 0.f;
            float su = x0 + x1;
#pragma unroll
            for (int off = 16; off > 0; off >>= 1)
                su += __shfl_xor_sync(0xffffffffu, su, off);
            const float inv = __fdividef(1.f, su);
            al0 = x0 * inv;        // alpha[lane]
            al1 = x1 * inv;        // alpha[lane+32]
        }

        // ---- wsum: issue batch 2, consume batch 1, consume batch 2 ----
        if (dow) {
            float v2[25];
#pragma unroll
            for (int j = 0; j < 25; j++) {
                const int id = curIds[(25 + j) * 3 + wpart];
                v2[j] = __ldg(ebase + (long long)id * D_);
            }
            float acc = 0.f;
#pragma unroll
            for (int j = 0; j < 25; j++) {
                const float al = (j < 32) ? __shfl_sync(0xffffffffu, al0, j)
                                          : __shfl_sync(0xffffffffu, al1, j - 32);
                acc += al * v1[j];
            }
#pragma unroll
            for (int j = 0; j < 25; j++) {
                const int k = 25 + j;
                const float al = (k < 32) ? __shfl_sync(0xffffffffu, al0, k)
                                          : __shfl_sync(0xffffffffu, al1, k - 32);
                acc += al * v2[j];
            }
            if (ht < 200) out[(long long)tile * 200 + ht] = acc;
        }
        // no trailing barrier: the next iteration's head BARH orders
        // sEp reads vs next epilogue writes and curIds reads vs next id stores.
        pp ^= 1;
    }
}

extern "C" void kernel_launch(void* const* d_in, const int* in_sizes, int n_in,
                              void* d_out, int out_size) {
    const unsigned int* ids = nullptr;
    const float *emb = nullptr, *Wht = nullptr, *Wrel = nullptr;
    const float *bht = nullptr, *brel = nullptr;

    for (int i = 0; i < n_in; i++) {
        const int sz = in_sizes[i];
        if      (sz == B_ * T_ * K_ * 3) ids  = (const unsigned int*)d_in[i];
        else if (sz == 500000 * D_)      emb  = (const float*)d_in[i];
        else if (sz == D_ * 2 * D_)      Wht  = (const float*)d_in[i];
        else if (sz == D_ * D_)          Wrel = (const float*)d_in[i];
        else if (sz == D_) {
            if (!bht) bht = (const float*)d_in[i];
            else      brel = (const float*)d_in[i];
        }
    }

    int dev = 0;
    cudaGetDevice(&dev);
    int sms = 148;
    cudaDeviceGetAttribute(&sms, cudaDevAttrMultiProcessorCount, dev);
    if (sms <= 0) sms = 148;

    cudaFuncSetAttribute(outer_encoder_mma,
                         cudaFuncAttributeMaxDynamicSharedMemorySize, SMEM_BYTES);
    outer_encoder_mma<<<sms, THREADS, SMEM_BYTES>>>(
        ids, emb, Wht, bht, Wrel, brel, (float*)d_out);
}